// round 2
// baseline (speedup 1.0000x reference)
#include <cuda_runtime.h>

#define N_NODES 50000
#define N_EDGES 1200000
#define N_REL   45
#define IN_C    64
#define HID_C   32
#define OUT_C   16

// Scratch (device globals: no allocation allowed in kernel_launch)
__device__ int   g_cnt[N_REL * N_NODES];   // per-(rel,dst) edge counts (9 MB)
__device__ float g_w[N_EDGES];             // per-edge weight 1/cnt
__device__ int   g_src[N_EDGES];
__device__ int   g_dst[N_EDGES];
__device__ int   g_rel[N_EDGES];
__device__ float g_h1[N_NODES * HID_C];    // layer-1 output (pre-ReLU)

// ---------------------------------------------------------------------------
__global__ void zero_cnt_kernel() {
    int i = blockIdx.x * blockDim.x + threadIdx.x;
    int stride = gridDim.x * blockDim.x;
    for (; i < N_REL * N_NODES; i += stride) g_cnt[i] = 0;
}

__global__ void prep_edges_kernel(const int* __restrict__ edge_index,
                                  const int* __restrict__ edge_type) {
    int e = blockIdx.x * blockDim.x + threadIdx.x;
    if (e >= N_EDGES) return;
    int src = edge_index[e];
    int dst = edge_index[N_EDGES + e];
    int rel = edge_type[e];
    g_src[e] = src;
    g_dst[e] = dst;
    g_rel[e] = rel;
    atomicAdd(&g_cnt[rel * N_NODES + dst], 1);
}

__global__ void weight_kernel() {
    int e = blockIdx.x * blockDim.x + threadIdx.x;
    if (e >= N_EDGES) return;
    int c = g_cnt[g_rel[e] * N_NODES + g_dst[e]];
    g_w[e] = 1.0f / (float)(c > 0 ? c : 1);
}

// ---------------------------------------------------------------------------
// h1[n, c] = b1[c] + sum_i x[n, i] * root1[i, c]
__global__ void root1_kernel(const float* __restrict__ x,
                             const float* __restrict__ root,
                             const float* __restrict__ b) {
    int t = blockIdx.x * blockDim.x + threadIdx.x;
    if (t >= N_NODES * HID_C) return;
    int n = t >> 5;
    int c = t & 31;
    float acc = b[c];
    const float4* xr = (const float4*)(x + n * IN_C);
#pragma unroll
    for (int i4 = 0; i4 < IN_C / 4; i4++) {
        float4 xv = xr[i4];
        acc += xv.x * root[(i4 * 4 + 0) * HID_C + c];
        acc += xv.y * root[(i4 * 4 + 1) * HID_C + c];
        acc += xv.z * root[(i4 * 4 + 2) * HID_C + c];
        acc += xv.w * root[(i4 * 4 + 3) * HID_C + c];
    }
    g_h1[t] = acc;
}

// out[n, c] = b2[c] + sum_i relu(h1[n, i]) * root2[i, c]
__global__ void root2_kernel(const float* __restrict__ root,
                             const float* __restrict__ b,
                             float* __restrict__ out) {
    int t = blockIdx.x * blockDim.x + threadIdx.x;
    if (t >= N_NODES * OUT_C) return;
    int n = t >> 4;
    int c = t & 15;
    float acc = b[c];
    const float4* hr = (const float4*)(g_h1 + n * HID_C);
#pragma unroll
    for (int i4 = 0; i4 < HID_C / 4; i4++) {
        float4 hv = hr[i4];
        acc += fmaxf(hv.x, 0.0f) * root[(i4 * 4 + 0) * OUT_C + c];
        acc += fmaxf(hv.y, 0.0f) * root[(i4 * 4 + 1) * OUT_C + c];
        acc += fmaxf(hv.z, 0.0f) * root[(i4 * 4 + 2) * OUT_C + c];
        acc += fmaxf(hv.w, 0.0f) * root[(i4 * 4 + 3) * OUT_C + c];
    }
    out[t] = acc;
}

// ---------------------------------------------------------------------------
// Layer-1 messages: blockIdx.x = relation, W column held in registers.
// Each warp scans 32-edge chunks; matched edges processed warp-collectively.
__global__ __launch_bounds__(256, 2)
void msg1_kernel(const float* __restrict__ x, const float* __restrict__ W1) {
    const int r    = blockIdx.x;
    const int lane = threadIdx.x & 31;
    const int warp = threadIdx.x >> 5;

    float Wreg[IN_C];
    const float* Wr = W1 + r * IN_C * HID_C;
#pragma unroll
    for (int i = 0; i < IN_C; i++) Wreg[i] = Wr[i * HID_C + lane];

    const int nchunks = N_EDGES / 32;
    int wg = blockIdx.y * 8 + warp;
    int nw = gridDim.y * 8;

    for (int ch = wg; ch < nchunks; ch += nw) {
        int e = ch * 32 + lane;
        unsigned mask = __ballot_sync(0xffffffffu, g_rel[e] == r);
        while (mask) {
            int j = __ffs(mask) - 1;
            mask &= mask - 1;
            int eb = ch * 32 + j;
            int s = g_src[eb];           // broadcast loads (same addr all lanes)
            int d = g_dst[eb];
            float wj = g_w[eb];
            const float4* xr = (const float4*)(x + s * IN_C);
            float acc = 0.0f;
#pragma unroll
            for (int i4 = 0; i4 < IN_C / 4; i4++) {
                float4 xv = xr[i4];
                acc += xv.x * Wreg[i4 * 4 + 0];
                acc += xv.y * Wreg[i4 * 4 + 1];
                acc += xv.z * Wreg[i4 * 4 + 2];
                acc += xv.w * Wreg[i4 * 4 + 3];
            }
            atomicAdd(&g_h1[d * HID_C + lane], acc * wj);
        }
    }
}

// Layer-2 messages: input = relu(h1). lane c = lane&15 (output channel),
// half = lane>>4 splits the 32-dim input reduction; combined via shfl.
__global__ __launch_bounds__(256, 2)
void msg2_kernel(const float* __restrict__ W2, float* __restrict__ out) {
    const int r    = blockIdx.x;
    const int lane = threadIdx.x & 31;
    const int warp = threadIdx.x >> 5;
    const int c    = lane & 15;
    const int half = lane >> 4;

    float Wreg[16];
    const float* Wr = W2 + r * HID_C * OUT_C;
#pragma unroll
    for (int k = 0; k < 16; k++) Wreg[k] = Wr[(half * 16 + k) * OUT_C + c];

    const int nchunks = N_EDGES / 32;
    int wg = blockIdx.y * 8 + warp;
    int nw = gridDim.y * 8;

    for (int ch = wg; ch < nchunks; ch += nw) {
        int e = ch * 32 + lane;
        unsigned mask = __ballot_sync(0xffffffffu, g_rel[e] == r);
        while (mask) {
            int j = __ffs(mask) - 1;
            mask &= mask - 1;
            int eb = ch * 32 + j;
            int s = g_src[eb];
            int d = g_dst[eb];
            float wj = g_w[eb];
            const float4* hr = (const float4*)(g_h1 + s * HID_C + half * 16);
            float acc = 0.0f;
#pragma unroll
            for (int k4 = 0; k4 < 4; k4++) {
                float4 hv = hr[k4];
                acc += fmaxf(hv.x, 0.0f) * Wreg[k4 * 4 + 0];
                acc += fmaxf(hv.y, 0.0f) * Wreg[k4 * 4 + 1];
                acc += fmaxf(hv.z, 0.0f) * Wreg[k4 * 4 + 2];
                acc += fmaxf(hv.w, 0.0f) * Wreg[k4 * 4 + 3];
            }
            acc += __shfl_down_sync(0xffffffffu, acc, 16);
            if (lane < 16) atomicAdd(&out[d * OUT_C + c], acc * wj);
        }
    }
}

// ---------------------------------------------------------------------------
extern "C" void kernel_launch(void* const* d_in, const int* in_sizes, int n_in,
                              void* d_out, int out_size) {
    const float* x          = (const float*)d_in[0];
    const int*   edge_index = (const int*)d_in[1];
    const int*   edge_type  = (const int*)d_in[2];
    const float* W1         = (const float*)d_in[3];
    const float* root1      = (const float*)d_in[4];
    const float* b1         = (const float*)d_in[5];
    const float* W2         = (const float*)d_in[6];
    const float* root2      = (const float*)d_in[7];
    const float* b2         = (const float*)d_in[8];
    float*       out        = (float*)d_out;

    (void)in_sizes; (void)n_in; (void)out_size;

    zero_cnt_kernel<<<2048, 256>>>();
    prep_edges_kernel<<<(N_EDGES + 255) / 256, 256>>>(edge_index, edge_type);
    weight_kernel<<<(N_EDGES + 255) / 256, 256>>>();

    root1_kernel<<<(N_NODES * HID_C + 255) / 256, 256>>>(x, root1, b1);
    msg1_kernel<<<dim3(N_REL, 24), 256>>>(x, W1);

    root2_kernel<<<(N_NODES * OUT_C + 255) / 256, 256>>>(root2, b2, out);
    msg2_kernel<<<dim3(N_REL, 24), 256>>>(W2, out);
}

// round 3
// speedup vs baseline: 1.0711x; 1.0711x over previous
#include <cuda_runtime.h>

#define N_NODES 50000
#define N_EDGES 1200000
#define N_REL   45
#define IN_C    64
#define HID_C   32
#define OUT_C   16

// Scratch (device globals: no allocation allowed in kernel_launch)
__device__ int   g_cnt[N_REL * N_NODES];   // per-(rel,dst) edge counts
__device__ int   g_hist[N_REL];            // per-relation edge counts
__device__ int   g_off[N_REL + 1];         // exclusive scan of g_hist
__device__ int   g_cursor[N_REL];          // scatter cursors
__device__ int   g_rel[N_EDGES];           // unsorted relation per edge
__device__ int   gs_src[N_EDGES];          // sorted-by-relation edge data
__device__ int   gs_dst[N_EDGES];
__device__ float gs_w[N_EDGES];
__device__ float g_h1[N_NODES * HID_C];    // layer-1 output (pre-ReLU)

// ---------------------------------------------------------------------------
__global__ void zero_kernel() {
    int i = blockIdx.x * blockDim.x + threadIdx.x;
    int stride = gridDim.x * blockDim.x;
    for (; i < N_REL * N_NODES; i += stride) g_cnt[i] = 0;
    if (blockIdx.x == 0 && threadIdx.x < N_REL) {
        g_hist[threadIdx.x] = 0;
    }
}

// counts per (rel,dst) and per-relation histogram (smem-staged)
__global__ void count_kernel(const int* __restrict__ edge_index,
                             const int* __restrict__ edge_type) {
    __shared__ int sh[N_REL];
    if (threadIdx.x < N_REL) sh[threadIdx.x] = 0;
    __syncthreads();
    int e = blockIdx.x * blockDim.x + threadIdx.x;
    if (e < N_EDGES) {
        int dst = edge_index[N_EDGES + e];
        int rel = edge_type[e];
        g_rel[e] = rel;
        atomicAdd(&g_cnt[rel * N_NODES + dst], 1);
        atomicAdd(&sh[rel], 1);
    }
    __syncthreads();
    if (threadIdx.x < N_REL) atomicAdd(&g_hist[threadIdx.x], sh[threadIdx.x]);
}

__global__ void scan_kernel() {
    if (threadIdx.x == 0) {
        int acc = 0;
        for (int r = 0; r < N_REL; r++) {
            g_off[r] = acc;
            g_cursor[r] = acc;
            acc += g_hist[r];
        }
        g_off[N_REL] = acc;
    }
}

// scatter edges into relation-sorted order; fold mean weight 1/cnt
__global__ void scatter_kernel(const int* __restrict__ edge_index) {
    int e = blockIdx.x * blockDim.x + threadIdx.x;
    if (e >= N_EDGES) return;
    int src = edge_index[e];
    int dst = edge_index[N_EDGES + e];
    int rel = g_rel[e];
    int pos = atomicAdd(&g_cursor[rel], 1);
    int c = g_cnt[rel * N_NODES + dst];
    gs_src[pos] = src;
    gs_dst[pos] = dst;
    gs_w[pos]   = 1.0f / (float)(c > 0 ? c : 1);
}

// ---------------------------------------------------------------------------
// h1[n, c] = b1[c] + sum_i x[n, i] * root1[i, c]
__global__ void root1_kernel(const float* __restrict__ x,
                             const float* __restrict__ root,
                             const float* __restrict__ b) {
    int t = blockIdx.x * blockDim.x + threadIdx.x;
    if (t >= N_NODES * HID_C) return;
    int n = t >> 5;
    int c = t & 31;
    float acc = b[c];
    const float4* xr = (const float4*)(x + n * IN_C);
#pragma unroll
    for (int i4 = 0; i4 < IN_C / 4; i4++) {
        float4 xv = xr[i4];
        acc += xv.x * root[(i4 * 4 + 0) * HID_C + c];
        acc += xv.y * root[(i4 * 4 + 1) * HID_C + c];
        acc += xv.z * root[(i4 * 4 + 2) * HID_C + c];
        acc += xv.w * root[(i4 * 4 + 3) * HID_C + c];
    }
    g_h1[t] = acc;
}

// out[n, c] = b2[c] + sum_i relu(h1[n, i]) * root2[i, c]
__global__ void root2_kernel(const float* __restrict__ root,
                             const float* __restrict__ b,
                             float* __restrict__ out) {
    int t = blockIdx.x * blockDim.x + threadIdx.x;
    if (t >= N_NODES * OUT_C) return;
    int n = t >> 4;
    int c = t & 15;
    float acc = b[c];
    const float4* hr = (const float4*)(g_h1 + n * HID_C);
#pragma unroll
    for (int i4 = 0; i4 < HID_C / 4; i4++) {
        float4 hv = hr[i4];
        acc += fmaxf(hv.x, 0.0f) * root[(i4 * 4 + 0) * OUT_C + c];
        acc += fmaxf(hv.y, 0.0f) * root[(i4 * 4 + 1) * OUT_C + c];
        acc += fmaxf(hv.z, 0.0f) * root[(i4 * 4 + 2) * OUT_C + c];
        acc += fmaxf(hv.w, 0.0f) * root[(i4 * 4 + 3) * OUT_C + c];
    }
    out[t] = acc;
}

// ---------------------------------------------------------------------------
// Layer-1 messages over relation-sorted edges. blockIdx.x = relation.
// W column register-resident (lane = output channel). Meta loaded coalesced
// once per 32 edges, redistributed via shfl.
__global__ __launch_bounds__(256, 2)
void msg1_kernel(const float* __restrict__ x, const float* __restrict__ W1) {
    const int r    = blockIdx.x;
    const int lane = threadIdx.x & 31;
    const int warp = threadIdx.x >> 5;

    float Wreg[IN_C];
    const float* Wr = W1 + r * IN_C * HID_C;
#pragma unroll
    for (int i = 0; i < IN_C; i++) Wreg[i] = Wr[i * HID_C + lane];

    const int segStart = g_off[r];
    const int segEnd   = g_off[r + 1];
    const int wg = blockIdx.y * 8 + warp;
    const int nw = gridDim.y * 8;

    for (int base = segStart + wg * 32; base < segEnd; base += nw * 32) {
        int n = segEnd - base; if (n > 32) n = 32;
        int s32 = 0, d32 = 0; float w32 = 0.0f;
        if (lane < n) {
            s32 = gs_src[base + lane];
            d32 = gs_dst[base + lane];
            w32 = gs_w[base + lane];
        }
        if (n == 32) {
#pragma unroll 4
            for (int j = 0; j < 32; j++) {
                int s = __shfl_sync(0xffffffffu, s32, j);
                int d = __shfl_sync(0xffffffffu, d32, j);
                float wj = __shfl_sync(0xffffffffu, w32, j);
                const float4* xr = (const float4*)(x + s * IN_C);
                float acc = 0.0f;
#pragma unroll
                for (int i4 = 0; i4 < IN_C / 4; i4++) {
                    float4 xv = xr[i4];
                    acc += xv.x * Wreg[i4 * 4 + 0];
                    acc += xv.y * Wreg[i4 * 4 + 1];
                    acc += xv.z * Wreg[i4 * 4 + 2];
                    acc += xv.w * Wreg[i4 * 4 + 3];
                }
                atomicAdd(&g_h1[d * HID_C + lane], acc * wj);
            }
        } else {
            for (int j = 0; j < n; j++) {
                int s = __shfl_sync(0xffffffffu, s32, j);
                int d = __shfl_sync(0xffffffffu, d32, j);
                float wj = __shfl_sync(0xffffffffu, w32, j);
                const float4* xr = (const float4*)(x + s * IN_C);
                float acc = 0.0f;
#pragma unroll
                for (int i4 = 0; i4 < IN_C / 4; i4++) {
                    float4 xv = xr[i4];
                    acc += xv.x * Wreg[i4 * 4 + 0];
                    acc += xv.y * Wreg[i4 * 4 + 1];
                    acc += xv.z * Wreg[i4 * 4 + 2];
                    acc += xv.w * Wreg[i4 * 4 + 3];
                }
                atomicAdd(&g_h1[d * HID_C + lane], acc * wj);
            }
        }
    }
}

// Layer-2 messages: input = relu(h1). c = lane&15 (output channel),
// half = lane>>4 splits the 32-dim reduction; combined via shfl.
__global__ __launch_bounds__(256, 2)
void msg2_kernel(const float* __restrict__ W2, float* __restrict__ out) {
    const int r    = blockIdx.x;
    const int lane = threadIdx.x & 31;
    const int warp = threadIdx.x >> 5;
    const int c    = lane & 15;
    const int half = lane >> 4;

    float Wreg[16];
    const float* Wr = W2 + r * HID_C * OUT_C;
#pragma unroll
    for (int k = 0; k < 16; k++) Wreg[k] = Wr[(half * 16 + k) * OUT_C + c];

    const int segStart = g_off[r];
    const int segEnd   = g_off[r + 1];
    const int wg = blockIdx.y * 8 + warp;
    const int nw = gridDim.y * 8;

    for (int base = segStart + wg * 32; base < segEnd; base += nw * 32) {
        int n = segEnd - base; if (n > 32) n = 32;
        int s32 = 0, d32 = 0; float w32 = 0.0f;
        if (lane < n) {
            s32 = gs_src[base + lane];
            d32 = gs_dst[base + lane];
            w32 = gs_w[base + lane];
        }
        for (int j = 0; j < n; j++) {
            int s = __shfl_sync(0xffffffffu, s32, j);
            int d = __shfl_sync(0xffffffffu, d32, j);
            float wj = __shfl_sync(0xffffffffu, w32, j);
            const float4* hr = (const float4*)(g_h1 + s * HID_C + half * 16);
            float acc = 0.0f;
#pragma unroll
            for (int k4 = 0; k4 < 4; k4++) {
                float4 hv = hr[k4];
                acc += fmaxf(hv.x, 0.0f) * Wreg[k4 * 4 + 0];
                acc += fmaxf(hv.y, 0.0f) * Wreg[k4 * 4 + 1];
                acc += fmaxf(hv.z, 0.0f) * Wreg[k4 * 4 + 2];
                acc += fmaxf(hv.w, 0.0f) * Wreg[k4 * 4 + 3];
            }
            acc += __shfl_down_sync(0xffffffffu, acc, 16);
            if (lane < 16) atomicAdd(&out[d * OUT_C + c], acc * wj);
        }
    }
}

// ---------------------------------------------------------------------------
extern "C" void kernel_launch(void* const* d_in, const int* in_sizes, int n_in,
                              void* d_out, int out_size) {
    const float* x          = (const float*)d_in[0];
    const int*   edge_index = (const int*)d_in[1];
    const int*   edge_type  = (const int*)d_in[2];
    const float* W1         = (const float*)d_in[3];
    const float* root1      = (const float*)d_in[4];
    const float* b1         = (const float*)d_in[5];
    const float* W2         = (const float*)d_in[6];
    const float* root2      = (const float*)d_in[7];
    const float* b2         = (const float*)d_in[8];
    float*       out        = (float*)d_out;

    (void)in_sizes; (void)n_in; (void)out_size;

    zero_kernel<<<2048, 256>>>();
    count_kernel<<<(N_EDGES + 255) / 256, 256>>>(edge_index, edge_type);
    scan_kernel<<<1, 32>>>();
    scatter_kernel<<<(N_EDGES + 255) / 256, 256>>>(edge_index);

    root1_kernel<<<(N_NODES * HID_C + 255) / 256, 256>>>(x, root1, b1);
    msg1_kernel<<<dim3(N_REL, 16), 256>>>(x, W1);

    root2_kernel<<<(N_NODES * OUT_C + 255) / 256, 256>>>(root2, b2, out);
    msg2_kernel<<<dim3(N_REL, 16), 256>>>(W2, out);
}

// round 4
// speedup vs baseline: 1.5371x; 1.4350x over previous
#include <cuda_runtime.h>

#define N_NODES 50000
#define N_EDGES 1200000
#define N_REL   45
#define IN_C    64
#define HID_C   32
#define OUT_C   16

#define SCAT_EPB 8192   // edges per scatter block

// Scratch (device globals: no allocation allowed in kernel_launch)
__device__ int   g_cnt[N_REL * N_NODES];   // per-(rel,dst) edge counts
__device__ int   g_hist[N_REL];            // per-relation edge counts
__device__ int   g_off[N_REL + 1];         // exclusive scan of g_hist
__device__ int   g_cursor[N_REL];          // scatter cursors
__device__ int   g_rel[N_EDGES];           // unsorted relation per edge
__device__ int   gs_src[N_EDGES];          // sorted-by-relation edge data
__device__ int   gs_dst[N_EDGES];
__device__ float gs_w[N_EDGES];
__device__ float g_h1[N_NODES * HID_C];    // layer-1 output (pre-ReLU)

// ---------------------------------------------------------------------------
__global__ void zero_kernel() {
    int i = blockIdx.x * blockDim.x + threadIdx.x;
    int stride = gridDim.x * blockDim.x;
    for (; i < N_REL * N_NODES; i += stride) g_cnt[i] = 0;
    if (blockIdx.x == 0 && threadIdx.x < N_REL) {
        g_hist[threadIdx.x] = 0;
    }
}

// counts per (rel,dst) and per-relation histogram (smem-staged)
__global__ void count_kernel(const int* __restrict__ edge_index,
                             const int* __restrict__ edge_type) {
    __shared__ int sh[N_REL];
    if (threadIdx.x < N_REL) sh[threadIdx.x] = 0;
    __syncthreads();
    int e = blockIdx.x * blockDim.x + threadIdx.x;
    if (e < N_EDGES) {
        int dst = edge_index[N_EDGES + e];
        int rel = edge_type[e];
        g_rel[e] = rel;
        atomicAdd(&g_cnt[rel * N_NODES + dst], 1);
        atomicAdd(&sh[rel], 1);
    }
    __syncthreads();
    if (threadIdx.x < N_REL) atomicAdd(&g_hist[threadIdx.x], sh[threadIdx.x]);
}

__global__ void scan_kernel() {
    if (threadIdx.x == 0) {
        int acc = 0;
        for (int r = 0; r < N_REL; r++) {
            g_off[r] = acc;
            g_cursor[r] = acc;
            acc += g_hist[r];
        }
        g_off[N_REL] = acc;
    }
}

// scatter edges into relation-sorted order; fold mean weight 1/cnt.
// Hierarchical cursors: one global atomicAdd per (block, relation) instead of
// one per edge (45-address global contention was 278us -> now ~6.6K atomics).
__global__ __launch_bounds__(256)
void scatter_kernel(const int* __restrict__ edge_index) {
    __shared__ int sh_cnt[N_REL];
    __shared__ int sh_base[N_REL];
    const int blockStart = blockIdx.x * SCAT_EPB;

    if (threadIdx.x < N_REL) sh_cnt[threadIdx.x] = 0;
    __syncthreads();

    // phase 1: block-local relation histogram
    for (int i = threadIdx.x; i < SCAT_EPB; i += blockDim.x) {
        int e = blockStart + i;
        if (e < N_EDGES) atomicAdd(&sh_cnt[g_rel[e]], 1);
    }
    __syncthreads();

    // phase 2: reserve contiguous ranges in global cursors
    if (threadIdx.x < N_REL) {
        sh_base[threadIdx.x] = atomicAdd(&g_cursor[threadIdx.x], sh_cnt[threadIdx.x]);
        sh_cnt[threadIdx.x] = 0;   // reuse as local cursor
    }
    __syncthreads();

    // phase 3: scatter using local cursors
    for (int i = threadIdx.x; i < SCAT_EPB; i += blockDim.x) {
        int e = blockStart + i;
        if (e >= N_EDGES) continue;
        int rel = g_rel[e];
        int pos = sh_base[rel] + atomicAdd(&sh_cnt[rel], 1);
        int src = edge_index[e];
        int dst = edge_index[N_EDGES + e];
        int c   = g_cnt[rel * N_NODES + dst];
        gs_src[pos] = src;
        gs_dst[pos] = dst;
        gs_w[pos]   = 1.0f / (float)(c > 0 ? c : 1);
    }
}

// ---------------------------------------------------------------------------
// h1[n, c] = b1[c] + sum_i x[n, i] * root1[i, c]
__global__ void root1_kernel(const float* __restrict__ x,
                             const float* __restrict__ root,
                             const float* __restrict__ b) {
    int t = blockIdx.x * blockDim.x + threadIdx.x;
    if (t >= N_NODES * HID_C) return;
    int n = t >> 5;
    int c = t & 31;
    float acc = b[c];
    const float4* xr = (const float4*)(x + n * IN_C);
#pragma unroll
    for (int i4 = 0; i4 < IN_C / 4; i4++) {
        float4 xv = xr[i4];
        acc += xv.x * root[(i4 * 4 + 0) * HID_C + c];
        acc += xv.y * root[(i4 * 4 + 1) * HID_C + c];
        acc += xv.z * root[(i4 * 4 + 2) * HID_C + c];
        acc += xv.w * root[(i4 * 4 + 3) * HID_C + c];
    }
    g_h1[t] = acc;
}

// out[n, c] = b2[c] + sum_i relu(h1[n, i]) * root2[i, c]
__global__ void root2_kernel(const float* __restrict__ root,
                             const float* __restrict__ b,
                             float* __restrict__ out) {
    int t = blockIdx.x * blockDim.x + threadIdx.x;
    if (t >= N_NODES * OUT_C) return;
    int n = t >> 4;
    int c = t & 15;
    float acc = b[c];
    const float4* hr = (const float4*)(g_h1 + n * HID_C);
#pragma unroll
    for (int i4 = 0; i4 < HID_C / 4; i4++) {
        float4 hv = hr[i4];
        acc += fmaxf(hv.x, 0.0f) * root[(i4 * 4 + 0) * OUT_C + c];
        acc += fmaxf(hv.y, 0.0f) * root[(i4 * 4 + 1) * OUT_C + c];
        acc += fmaxf(hv.z, 0.0f) * root[(i4 * 4 + 2) * OUT_C + c];
        acc += fmaxf(hv.w, 0.0f) * root[(i4 * 4 + 3) * OUT_C + c];
    }
    out[t] = acc;
}

// ---------------------------------------------------------------------------
// Layer-1 messages over relation-sorted edges. blockIdx.x = relation.
// W column register-resident (lane = output channel). Meta loaded coalesced
// once per 32 edges, redistributed via shfl.
__global__ __launch_bounds__(256, 2)
void msg1_kernel(const float* __restrict__ x, const float* __restrict__ W1) {
    const int r    = blockIdx.x;
    const int lane = threadIdx.x & 31;
    const int warp = threadIdx.x >> 5;

    float Wreg[IN_C];
    const float* Wr = W1 + r * IN_C * HID_C;
#pragma unroll
    for (int i = 0; i < IN_C; i++) Wreg[i] = Wr[i * HID_C + lane];

    const int segStart = g_off[r];
    const int segEnd   = g_off[r + 1];
    const int wg = blockIdx.y * 8 + warp;
    const int nw = gridDim.y * 8;

    for (int base = segStart + wg * 32; base < segEnd; base += nw * 32) {
        int n = segEnd - base; if (n > 32) n = 32;
        int s32 = 0, d32 = 0; float w32 = 0.0f;
        if (lane < n) {
            s32 = gs_src[base + lane];
            d32 = gs_dst[base + lane];
            w32 = gs_w[base + lane];
        }
        if (n == 32) {
#pragma unroll 4
            for (int j = 0; j < 32; j++) {
                int s = __shfl_sync(0xffffffffu, s32, j);
                int d = __shfl_sync(0xffffffffu, d32, j);
                float wj = __shfl_sync(0xffffffffu, w32, j);
                const float4* xr = (const float4*)(x + s * IN_C);
                float acc = 0.0f;
#pragma unroll
                for (int i4 = 0; i4 < IN_C / 4; i4++) {
                    float4 xv = xr[i4];
                    acc += xv.x * Wreg[i4 * 4 + 0];
                    acc += xv.y * Wreg[i4 * 4 + 1];
                    acc += xv.z * Wreg[i4 * 4 + 2];
                    acc += xv.w * Wreg[i4 * 4 + 3];
                }
                atomicAdd(&g_h1[d * HID_C + lane], acc * wj);
            }
        } else {
            for (int j = 0; j < n; j++) {
                int s = __shfl_sync(0xffffffffu, s32, j);
                int d = __shfl_sync(0xffffffffu, d32, j);
                float wj = __shfl_sync(0xffffffffu, w32, j);
                const float4* xr = (const float4*)(x + s * IN_C);
                float acc = 0.0f;
#pragma unroll
                for (int i4 = 0; i4 < IN_C / 4; i4++) {
                    float4 xv = xr[i4];
                    acc += xv.x * Wreg[i4 * 4 + 0];
                    acc += xv.y * Wreg[i4 * 4 + 1];
                    acc += xv.z * Wreg[i4 * 4 + 2];
                    acc += xv.w * Wreg[i4 * 4 + 3];
                }
                atomicAdd(&g_h1[d * HID_C + lane], acc * wj);
            }
        }
    }
}

// Layer-2 messages: input = relu(h1). c = lane&15 (output channel),
// half = lane>>4 splits the 32-dim reduction; combined via shfl.
__global__ __launch_bounds__(256, 2)
void msg2_kernel(const float* __restrict__ W2, float* __restrict__ out) {
    const int r    = blockIdx.x;
    const int lane = threadIdx.x & 31;
    const int warp = threadIdx.x >> 5;
    const int c    = lane & 15;
    const int half = lane >> 4;

    float Wreg[16];
    const float* Wr = W2 + r * HID_C * OUT_C;
#pragma unroll
    for (int k = 0; k < 16; k++) Wreg[k] = Wr[(half * 16 + k) * OUT_C + c];

    const int segStart = g_off[r];
    const int segEnd   = g_off[r + 1];
    const int wg = blockIdx.y * 8 + warp;
    const int nw = gridDim.y * 8;

    for (int base = segStart + wg * 32; base < segEnd; base += nw * 32) {
        int n = segEnd - base; if (n > 32) n = 32;
        int s32 = 0, d32 = 0; float w32 = 0.0f;
        if (lane < n) {
            s32 = gs_src[base + lane];
            d32 = gs_dst[base + lane];
            w32 = gs_w[base + lane];
        }
        for (int j = 0; j < n; j++) {
            int s = __shfl_sync(0xffffffffu, s32, j);
            int d = __shfl_sync(0xffffffffu, d32, j);
            float wj = __shfl_sync(0xffffffffu, w32, j);
            const float4* hr = (const float4*)(g_h1 + s * HID_C + half * 16);
            float acc = 0.0f;
#pragma unroll
            for (int k4 = 0; k4 < 4; k4++) {
                float4 hv = hr[k4];
                acc += fmaxf(hv.x, 0.0f) * Wreg[k4 * 4 + 0];
                acc += fmaxf(hv.y, 0.0f) * Wreg[k4 * 4 + 1];
                acc += fmaxf(hv.z, 0.0f) * Wreg[k4 * 4 + 2];
                acc += fmaxf(hv.w, 0.0f) * Wreg[k4 * 4 + 3];
            }
            acc += __shfl_down_sync(0xffffffffu, acc, 16);
            if (lane < 16) atomicAdd(&out[d * OUT_C + c], acc * wj);
        }
    }
}

// ---------------------------------------------------------------------------
extern "C" void kernel_launch(void* const* d_in, const int* in_sizes, int n_in,
                              void* d_out, int out_size) {
    const float* x          = (const float*)d_in[0];
    const int*   edge_index = (const int*)d_in[1];
    const int*   edge_type  = (const int*)d_in[2];
    const float* W1         = (const float*)d_in[3];
    const float* root1      = (const float*)d_in[4];
    const float* b1         = (const float*)d_in[5];
    const float* W2         = (const float*)d_in[6];
    const float* root2      = (const float*)d_in[7];
    const float* b2         = (const float*)d_in[8];
    float*       out        = (float*)d_out;

    (void)in_sizes; (void)n_in; (void)out_size;

    zero_kernel<<<2048, 256>>>();
    count_kernel<<<(N_EDGES + 255) / 256, 256>>>(edge_index, edge_type);
    scan_kernel<<<1, 32>>>();
    scatter_kernel<<<(N_EDGES + SCAT_EPB - 1) / SCAT_EPB, 256>>>(edge_index);

    root1_kernel<<<(N_NODES * HID_C + 255) / 256, 256>>>(x, root1, b1);
    msg1_kernel<<<dim3(N_REL, 16), 256>>>(x, W1);

    root2_kernel<<<(N_NODES * OUT_C + 255) / 256, 256>>>(root2, b2, out);
    msg2_kernel<<<dim3(N_REL, 16), 256>>>(W2, out);
}